// round 1
// baseline (speedup 1.0000x reference)
#include <cuda_runtime.h>
#include <cstdint>

// ---------------------------------------------------------------------------
// Problem: q[4,2048,1024] f32, k[8192,1024] f32, v[8192,1024] f32
//   S = q @ k^T                      [8192, 8192]
//   G = gelu_exact(S / ||S||_row * sqrt(8192))
//   out = G @ v                      [8192, 1024] f32
//
// Plan: tf32 mma.sync GEMMs (precision-safe vs 1e-3), S in __device__ scratch,
// norm+gelu fused in-place, v transposed once so both GEMMs share one kernel.
// ---------------------------------------------------------------------------

static __device__ float g_S[8192ull * 8192ull];   // 256 MB scratch (scores/gated)
static __device__ float g_VT[1024ull * 8192ull];  // 32 MB  v^T

__device__ __forceinline__ uint32_t f2tf32(float x) {
    uint32_t u;
    asm("cvt.rna.tf32.f32 %0, %1;" : "=r"(u) : "f"(x));
    return u;
}

// ---------------------------------------------------------------------------
// GEMM: C[M,N] = A[M,K] * B[N,K]^T   (both operands K-major, fp32->tf32)
// Block tile 128x128x32, 8 warps (4 in M, 2 in N), warp tile 32x64.
// ---------------------------------------------------------------------------
constexpr int BM = 128, BN = 128, BK = 32, SPAD = 4;
constexpr int SLD = BK + SPAD;  // 36 words row stride (16B aligned, conflict-free frags)

__global__ __launch_bounds__(256) void gemm_tf32_kernel(
    const float* __restrict__ A, const float* __restrict__ B, float* __restrict__ C,
    int M, int N, int K)
{
    __shared__ float As[BM][SLD];
    __shared__ float Bs[BN][SLD];

    const int tid  = threadIdx.x;
    const int lane = tid & 31;
    const int wid  = tid >> 5;
    const int wm   = wid & 3;   // 0..3 along M
    const int wn   = wid >> 2;  // 0..1 along N
    const long bm = (long)blockIdx.y * BM;
    const long bn = (long)blockIdx.x * BN;

    float acc[2][8][4];
#pragma unroll
    for (int i = 0; i < 2; i++)
#pragma unroll
        for (int j = 0; j < 8; j++)
#pragma unroll
            for (int c = 0; c < 4; c++) acc[i][j][c] = 0.f;

    const uint32_t* As_u = reinterpret_cast<const uint32_t*>(&As[0][0]);
    const uint32_t* Bs_u = reinterpret_cast<const uint32_t*>(&Bs[0][0]);

    for (int k0 = 0; k0 < K; k0 += BK) {
        // ---- load 128x32 f32 tiles of A and B, round to tf32 in smem ----
#pragma unroll
        for (int i = 0; i < 4; i++) {
            int idx = tid + i * 256;          // 0..1023
            int row = idx >> 3;               // 0..127
            int c4  = (idx & 7) << 2;         // 0,4,...,28
            float4 va = *reinterpret_cast<const float4*>(&A[(size_t)(bm + row) * K + k0 + c4]);
            float4 vb = *reinterpret_cast<const float4*>(&B[(size_t)(bn + row) * K + k0 + c4]);
            uint4 ua = make_uint4(f2tf32(va.x), f2tf32(va.y), f2tf32(va.z), f2tf32(va.w));
            uint4 ub = make_uint4(f2tf32(vb.x), f2tf32(vb.y), f2tf32(vb.z), f2tf32(vb.w));
            *reinterpret_cast<uint4*>(&As[row][c4]) = ua;
            *reinterpret_cast<uint4*>(&Bs[row][c4]) = ub;
        }
        __syncthreads();

        // ---- 4 k-steps of m16n8k8 tf32 mma ----
#pragma unroll
        for (int ks = 0; ks < 4; ks++) {
            const int kk = ks * 8;
            uint32_t afr[2][4];
#pragma unroll
            for (int mt = 0; mt < 2; mt++) {
                int r = wm * 32 + mt * 16 + (lane >> 2);
                afr[mt][0] = As_u[(r    ) * SLD + kk     + (lane & 3)];
                afr[mt][1] = As_u[(r + 8) * SLD + kk     + (lane & 3)];
                afr[mt][2] = As_u[(r    ) * SLD + kk + 4 + (lane & 3)];
                afr[mt][3] = As_u[(r + 8) * SLD + kk + 4 + (lane & 3)];
            }
#pragma unroll
            for (int nt = 0; nt < 8; nt++) {
                int cidx = wn * 64 + nt * 8 + (lane >> 2);
                uint32_t b0 = Bs_u[cidx * SLD + kk     + (lane & 3)];
                uint32_t b1 = Bs_u[cidx * SLD + kk + 4 + (lane & 3)];
#pragma unroll
                for (int mt = 0; mt < 2; mt++) {
                    asm volatile(
                        "mma.sync.aligned.m16n8k8.row.col.f32.tf32.tf32.f32 "
                        "{%0,%1,%2,%3}, {%4,%5,%6,%7}, {%8,%9}, {%0,%1,%2,%3};\n"
                        : "+f"(acc[mt][nt][0]), "+f"(acc[mt][nt][1]),
                          "+f"(acc[mt][nt][2]), "+f"(acc[mt][nt][3])
                        : "r"(afr[mt][0]), "r"(afr[mt][1]),
                          "r"(afr[mt][2]), "r"(afr[mt][3]),
                          "r"(b0), "r"(b1));
                }
            }
        }
        __syncthreads();
    }

    // ---- epilogue: fp32 stores ----
#pragma unroll
    for (int mt = 0; mt < 2; mt++) {
        long r0 = bm + wm * 32 + mt * 16 + (lane >> 2);
#pragma unroll
        for (int nt = 0; nt < 8; nt++) {
            long c0 = bn + wn * 64 + nt * 8 + (lane & 3) * 2;
            *reinterpret_cast<float2*>(&C[(size_t)r0 * N + c0]) =
                make_float2(acc[mt][nt][0], acc[mt][nt][1]);
            *reinterpret_cast<float2*>(&C[(size_t)(r0 + 8) * N + c0]) =
                make_float2(acc[mt][nt][2], acc[mt][nt][3]);
        }
    }
}

// ---------------------------------------------------------------------------
// Row-wise L2 norm * sqrt(N) + exact (erf) GELU, in place. One block per row.
// ---------------------------------------------------------------------------
__global__ __launch_bounds__(256) void norm_gelu_kernel(float* __restrict__ S, int N)
{
    float* p = S + (size_t)blockIdx.x * N;
    float ss = 0.f;
    for (int i = threadIdx.x; i < N; i += 256) {
        float x = p[i];
        ss += x * x;
    }
    __shared__ float red[8];
#pragma unroll
    for (int o = 16; o > 0; o >>= 1) ss += __shfl_xor_sync(0xffffffffu, ss, o);
    if ((threadIdx.x & 31) == 0) red[threadIdx.x >> 5] = ss;
    __syncthreads();
    if (threadIdx.x < 32) {
        float v = (threadIdx.x < 8) ? red[threadIdx.x] : 0.f;
#pragma unroll
        for (int o = 4; o > 0; o >>= 1) v += __shfl_xor_sync(0xffffffffu, v, o);
        if (threadIdx.x == 0) red[0] = v;
    }
    __syncthreads();
    const float scale = sqrtf((float)N / red[0]);
    for (int i = threadIdx.x; i < N; i += 256) {
        float x = p[i] * scale;
        p[i] = 0.5f * x * (1.f + erff(x * 0.70710678118654752440f));
    }
}

// ---------------------------------------------------------------------------
// Transpose v[8192,1024] -> vT[1024,8192]
// ---------------------------------------------------------------------------
__global__ __launch_bounds__(256) void transpose_kernel(
    const float* __restrict__ V, float* __restrict__ VT, int R, int Ccols)
{
    __shared__ float t[32][33];
    int c0 = blockIdx.x * 32, r0 = blockIdx.y * 32;
    int x = threadIdx.x, y = threadIdx.y;  // block (32,8)
#pragma unroll
    for (int j = 0; j < 32; j += 8)
        t[y + j][x] = V[(size_t)(r0 + y + j) * Ccols + c0 + x];
    __syncthreads();
#pragma unroll
    for (int j = 0; j < 32; j += 8)
        VT[(size_t)(c0 + y + j) * R + r0 + x] = t[x][y + j];
}

// ---------------------------------------------------------------------------
extern "C" void kernel_launch(void* const* d_in, const int* in_sizes, int n_in,
                              void* d_out, int out_size)
{
    const float* q = (const float*)d_in[0];   // [8192, 1024]
    const float* k = (const float*)d_in[1];   // [8192, 1024]
    const float* v = (const float*)d_in[2];   // [8192, 1024]
    float* out = (float*)d_out;               // [8192, 1024]

    float *S = nullptr, *VT = nullptr;
    cudaGetSymbolAddress((void**)&S, g_S);
    cudaGetSymbolAddress((void**)&VT, g_VT);

    const int M = 8192, NBANK = 8192, D = 1024;

    // v^T (needed only by GEMM2, can run first)
    transpose_kernel<<<dim3(D / 32, NBANK / 32), dim3(32, 8)>>>(v, VT, NBANK, D);

    // S = q @ k^T   (M=8192, N=8192, K=1024)
    gemm_tf32_kernel<<<dim3(NBANK / BN, M / BM), 256>>>(q, k, S, M, NBANK, D);

    // row-norm * sqrt(N) + exact gelu, in place
    norm_gelu_kernel<<<M, 256>>>(S, NBANK);

    // out = G @ vT^T  (M=8192, N=1024, K=8192)
    gemm_tf32_kernel<<<dim3(D / BN, M / BM), 256>>>(S, VT, out, M, D, NBANK);
}

// round 2
// speedup vs baseline: 1.6755x; 1.6755x over previous
#include <cuda_runtime.h>
#include <cstdint>

// ---------------------------------------------------------------------------
// S = q @ k^T  [8192,8192];  G = gelu_exact(S/||S||_row*sqrt(8192));
// out = G @ v  [8192,1024].  tf32 mma.sync, cp.async 3-stage pipeline.
// ---------------------------------------------------------------------------

static __device__ float g_S[8192ull * 8192ull];   // 256 MB scratch
static __device__ float g_VT[1024ull * 8192ull];  // 32 MB  v^T

constexpr int BM = 128, BN = 128, BK = 32, SPAD = 4;
constexpr int SLD = BK + SPAD;          // 36 words; conflict-free frag pattern
constexpr int STAGES = 3;
constexpr int TILEA = BM * SLD;         // floats per A (or B) tile
constexpr int TILE2 = 2 * TILEA;        // A + B per stage
constexpr unsigned SMEM_BYTES = STAGES * TILE2 * 4;  // 110,592 B

__device__ __forceinline__ uint32_t f2tf32(float x) {
    uint32_t u;
    asm("cvt.rna.tf32.f32 %0, %1;" : "=r"(u) : "f"(x));
    return u;
}

__device__ __forceinline__ void cp16(float* dst, const float* src) {
    uint32_t d = (uint32_t)__cvta_generic_to_shared(dst);
    asm volatile("cp.async.cg.shared.global [%0], [%1], 16;\n" :: "r"(d), "l"(src));
}

__global__ __launch_bounds__(256, 2) void gemm_tf32_pipe(
    const float* __restrict__ A, const float* __restrict__ B, float* __restrict__ C,
    int M, int N, int K)
{
    extern __shared__ float smem[];

    const int tid  = threadIdx.x;
    const int lane = tid & 31;
    const int wid  = tid >> 5;
    const int wm   = wid & 3;     // 0..3 along M
    const int wn   = wid >> 2;    // 0..1 along N
    const long bm = (long)blockIdx.y * BM;
    const long bn = (long)blockIdx.x * BN;

    float acc[2][8][4];
#pragma unroll
    for (int i = 0; i < 2; i++)
#pragma unroll
        for (int j = 0; j < 8; j++)
#pragma unroll
            for (int c = 0; c < 4; c++) acc[i][j][c] = 0.f;

    const int nk = K / BK;

    // ---- issue loads for first STAGES-1 stages ----
#pragma unroll
    for (int s = 0; s < STAGES - 1; s++) {
        float* As = smem + s * TILE2;
        float* Bs = As + TILEA;
        const int k0 = s * BK;
#pragma unroll
        for (int i = 0; i < 4; i++) {
            int idx = tid + i * 256;
            int row = idx >> 3;
            int c4  = (idx & 7) << 2;
            cp16(&As[row * SLD + c4], &A[(size_t)(bm + row) * K + k0 + c4]);
            cp16(&Bs[row * SLD + c4], &B[(size_t)(bn + row) * K + k0 + c4]);
        }
        asm volatile("cp.async.commit_group;\n");
    }

    for (int kt = 0; kt < nk; kt++) {
        asm volatile("cp.async.wait_group %0;\n" :: "n"(STAGES - 2));
        __syncthreads();

        // issue load for stage kt+STAGES-1 (or empty commit to keep count)
        if (kt + STAGES - 1 < nk) {
            const int s = (kt + STAGES - 1) % STAGES;
            float* As = smem + s * TILE2;
            float* Bs = As + TILEA;
            const int k0 = (kt + STAGES - 1) * BK;
#pragma unroll
            for (int i = 0; i < 4; i++) {
                int idx = tid + i * 256;
                int row = idx >> 3;
                int c4  = (idx & 7) << 2;
                cp16(&As[row * SLD + c4], &A[(size_t)(bm + row) * K + k0 + c4]);
                cp16(&Bs[row * SLD + c4], &B[(size_t)(bn + row) * K + k0 + c4]);
            }
            asm volatile("cp.async.commit_group;\n");
        } else {
            asm volatile("cp.async.commit_group;\n");
        }

        // ---- compute on stage kt%STAGES ----
        const float* As = smem + (kt % STAGES) * TILE2;
        const float* Bs = As + TILEA;

#pragma unroll
        for (int ks = 0; ks < 4; ks++) {
            const int kk = ks * 8;
            uint32_t afr[2][4];
#pragma unroll
            for (int mt = 0; mt < 2; mt++) {
                int r = wm * 32 + mt * 16 + (lane >> 2);
                afr[mt][0] = f2tf32(As[(r    ) * SLD + kk     + (lane & 3)]);
                afr[mt][1] = f2tf32(As[(r + 8) * SLD + kk     + (lane & 3)]);
                afr[mt][2] = f2tf32(As[(r    ) * SLD + kk + 4 + (lane & 3)]);
                afr[mt][3] = f2tf32(As[(r + 8) * SLD + kk + 4 + (lane & 3)]);
            }
#pragma unroll
            for (int nt = 0; nt < 8; nt++) {
                int cidx = wn * 64 + nt * 8 + (lane >> 2);
                uint32_t b0 = f2tf32(Bs[cidx * SLD + kk     + (lane & 3)]);
                uint32_t b1 = f2tf32(Bs[cidx * SLD + kk + 4 + (lane & 3)]);
#pragma unroll
                for (int mt = 0; mt < 2; mt++) {
                    asm volatile(
                        "mma.sync.aligned.m16n8k8.row.col.f32.tf32.tf32.f32 "
                        "{%0,%1,%2,%3}, {%4,%5,%6,%7}, {%8,%9}, {%0,%1,%2,%3};\n"
                        : "+f"(acc[mt][nt][0]), "+f"(acc[mt][nt][1]),
                          "+f"(acc[mt][nt][2]), "+f"(acc[mt][nt][3])
                        : "r"(afr[mt][0]), "r"(afr[mt][1]),
                          "r"(afr[mt][2]), "r"(afr[mt][3]),
                          "r"(b0), "r"(b1));
                }
            }
        }
    }

    // ---- epilogue ----
#pragma unroll
    for (int mt = 0; mt < 2; mt++) {
        long r0 = bm + wm * 32 + mt * 16 + (lane >> 2);
#pragma unroll
        for (int nt = 0; nt < 8; nt++) {
            long c0 = bn + wn * 64 + nt * 8 + (lane & 3) * 2;
            *reinterpret_cast<float2*>(&C[(size_t)r0 * N + c0]) =
                make_float2(acc[mt][nt][0], acc[mt][nt][1]);
            *reinterpret_cast<float2*>(&C[(size_t)(r0 + 8) * N + c0]) =
                make_float2(acc[mt][nt][2], acc[mt][nt][3]);
        }
    }
}

// ---------------------------------------------------------------------------
// Row-wise L2 norm * sqrt(N) + exact GELU, in place. Vectorized float4.
// ---------------------------------------------------------------------------
__global__ __launch_bounds__(256) void norm_gelu_kernel(float* __restrict__ S, int N)
{
    float4* p = reinterpret_cast<float4*>(S + (size_t)blockIdx.x * N);
    const int n4 = N >> 2;
    float ss = 0.f;
    for (int i = threadIdx.x; i < n4; i += 256) {
        float4 x = p[i];
        ss += x.x * x.x + x.y * x.y + x.z * x.z + x.w * x.w;
    }
    __shared__ float red[8];
#pragma unroll
    for (int o = 16; o > 0; o >>= 1) ss += __shfl_xor_sync(0xffffffffu, ss, o);
    if ((threadIdx.x & 31) == 0) red[threadIdx.x >> 5] = ss;
    __syncthreads();
    if (threadIdx.x < 32) {
        float v = (threadIdx.x < 8) ? red[threadIdx.x] : 0.f;
#pragma unroll
        for (int o = 4; o > 0; o >>= 1) v += __shfl_xor_sync(0xffffffffu, v, o);
        if (threadIdx.x == 0) red[0] = v;
    }
    __syncthreads();
    const float scale = sqrtf((float)N / red[0]);
    const float inv_sqrt2 = 0.70710678118654752440f;
    for (int i = threadIdx.x; i < n4; i += 256) {
        float4 x = p[i];
        x.x *= scale; x.y *= scale; x.z *= scale; x.w *= scale;
        x.x = 0.5f * x.x * (1.f + erff(x.x * inv_sqrt2));
        x.y = 0.5f * x.y * (1.f + erff(x.y * inv_sqrt2));
        x.z = 0.5f * x.z * (1.f + erff(x.z * inv_sqrt2));
        x.w = 0.5f * x.w * (1.f + erff(x.w * inv_sqrt2));
        p[i] = x;
    }
}

// ---------------------------------------------------------------------------
// Transpose v[8192,1024] -> vT[1024,8192]
// ---------------------------------------------------------------------------
__global__ __launch_bounds__(256) void transpose_kernel(
    const float* __restrict__ V, float* __restrict__ VT, int R, int Ccols)
{
    __shared__ float t[32][33];
    int c0 = blockIdx.x * 32, r0 = blockIdx.y * 32;
    int x = threadIdx.x, y = threadIdx.y;  // block (32,8)
#pragma unroll
    for (int j = 0; j < 32; j += 8)
        t[y + j][x] = V[(size_t)(r0 + y + j) * Ccols + c0 + x];
    __syncthreads();
#pragma unroll
    for (int j = 0; j < 32; j += 8)
        VT[(size_t)(c0 + y + j) * R + r0 + x] = t[x][y + j];
}

// ---------------------------------------------------------------------------
extern "C" void kernel_launch(void* const* d_in, const int* in_sizes, int n_in,
                              void* d_out, int out_size)
{
    const float* q = (const float*)d_in[0];   // [8192, 1024]
    const float* k = (const float*)d_in[1];   // [8192, 1024]
    const float* v = (const float*)d_in[2];   // [8192, 1024]
    float* out = (float*)d_out;               // [8192, 1024]

    float *S = nullptr, *VT = nullptr;
    cudaGetSymbolAddress((void**)&S, g_S);
    cudaGetSymbolAddress((void**)&VT, g_VT);

    static bool attr_done = false;
    if (!attr_done) {
        cudaFuncSetAttribute(gemm_tf32_pipe,
                             cudaFuncAttributeMaxDynamicSharedMemorySize, SMEM_BYTES);
        attr_done = true;
    }

    const int M = 8192, NBANK = 8192, D = 1024;

    transpose_kernel<<<dim3(D / 32, NBANK / 32), dim3(32, 8)>>>(v, VT, NBANK, D);

    // S = q @ k^T
    gemm_tf32_pipe<<<dim3(NBANK / BN, M / BM), 256, SMEM_BYTES>>>(q, k, S, M, NBANK, D);

    // norm + gelu in place
    norm_gelu_kernel<<<M, 256>>>(S, NBANK);

    // out = G @ vT^T
    gemm_tf32_pipe<<<dim3(D / BN, M / BM), 256, SMEM_BYTES>>>(S, VT, out, M, D, NBANK);
}